// round 14
// baseline (speedup 1.0000x reference)
#include <cuda_runtime.h>
#include <stdint.h>
#include <math.h>

#define NB   296
#define NT   256
#define RP   68                 // global padded row stride (17 float4)
#define HSP  (512*RP)
#define LSZ  (65*RP)
#define ULL  unsigned long long

// ------------------------- scratch (device globals) -------------------------
__device__ float g_y[HSP];             // current y [512][68] (pad cols always 0)
__device__ float g_P[8][9][HSP];       // kqv partials [kz][mat]
__device__ float g_Lp[8][3][LSZ];      // logits partials [hcc][slot]
__device__ float g_C[65*1536];         // concat buffer
__device__ float g_lp[24][HSP];        // linear partials [cc]
__device__ float g_zp[8][1024];
__device__ float g_t[512];
__device__ ULL   g_bar[24];

// ------------------------- helpers ------------------------------------------
#define FMA2(acc, a, b) asm("fma.rn.f32x2 %0, %1, %2, %0;" : "+l"(acc) : "l"(a), "l"(b))
#define PACK2(d, x)     asm("mov.b64 %0, {%1, %1};" : "=l"(d) : "f"(x))
#define UNPK2(lo, hi, v) asm("mov.b64 {%0, %1}, %2;" : "=f"(lo), "=f"(hi) : "l"(v))

#define MMA_TF32(d, a0, a1, a2, a3, b0, b1) \
    asm("mma.sync.aligned.m16n8k8.row.col.f32.tf32.tf32.f32 " \
        "{%0,%1,%2,%3}, {%4,%5,%6,%7}, {%8,%9}, {%0,%1,%2,%3};" \
        : "+f"(d[0]), "+f"(d[1]), "+f"(d[2]), "+f"(d[3]) \
        : "r"(a0), "r"(a1), "r"(a2), "r"(a3), "r"(b0), "r"(b1))

__device__ __forceinline__ float tf32r(float f) {
    uint32_t u;
    asm("cvt.rna.tf32.f32 %0, %1;" : "=r"(u) : "f"(f));
    return __uint_as_float(u);
}
__device__ __forceinline__ uint32_t tf32u(float f) {
    uint32_t u;
    asm("cvt.rna.tf32.f32 %0, %1;" : "=r"(u) : "f"(f));
    return u;
}
__device__ __forceinline__ float4 tf32r4(float4 v) {
    return make_float4(tf32r(v.x), tf32r(v.y), tf32r(v.z), tf32r(v.w));
}

__device__ __forceinline__ void gbar(int k) {
    __threadfence();
    __syncthreads();
    if (threadIdx.x == 0) {
        ULL* p = &g_bar[k];
        ULL old, cur;
        asm volatile("atom.release.gpu.add.u64 %0, [%1], 1;"
                     : "=l"(old) : "l"(p) : "memory");
        ULL target = old - (old % (ULL)NB) + (ULL)NB;
        do {
            asm volatile("ld.acquire.gpu.u64 %0, [%1];"
                         : "=l"(cur) : "l"(p) : "memory");
        } while (cur < target);
    }
    __syncthreads();
}

__device__ __forceinline__ void pf_range(const float* p, int nfloat) {
    int lines = nfloat >> 5;
    for (int i = blockIdx.x * NT + threadIdx.x; i < lines; i += NB * NT)
        asm volatile("prefetch.global.L2 [%0];" :: "l"(p + (i << 5)));
}

// shared pool (floats):
// GEMM: B0[1152] B1[1152] Tr[4608] = 6912
// LOGITS Ks[4352] Qs[4352] Sm[4420] = 13124 ; ATT Ls[4420] Vs[2176] = 6596
#define SMEM_F 13124

// =============================================================================
// GEMM item via tf32 mma.sync m16n8k8. Warp w owns (mf=w&3, kf=w>>2).
// A: loaded DIRECTLY from global into per-warp registers (2-chunk prefetch).
// B: regs -> smem double buffer (1-chunk-early load, MMA-before-store).
// MODE 0: A row-major W[m*512+k], B = g_y (padded). MODE 1: A k-major, B = g_C.
// =============================================================================
template<int MODE>
__device__ __forceinline__ void a_prefetch(const float* __restrict__ A,
        int mbase, int kb, int mc, int kr, int tig, float4& af) {
    if (MODE == 0) {
        af.x = A[(mbase + mc) * 512 + kb + kr + tig];
        af.y = A[(mbase + mc + 8) * 512 + kb + kr + tig];
        af.z = A[(mbase + mc) * 512 + kb + kr + tig + 4];
        af.w = A[(mbase + mc + 8) * 512 + kb + kr + tig + 4];
    } else {
        af.x = A[(kb + kr + tig) * 512 + mbase + mc];
        af.y = A[(kb + kr + tig) * 512 + mbase + mc + 8];
        af.z = A[(kb + kr + tig + 4) * 512 + mbase + mc];
        af.w = A[(kb + kr + tig + 4) * 512 + mbase + mc + 8];
    }
}

template<int MODE>
__device__ __forceinline__ void b_prefetch(int kb, float4& b4, float4& be) {
    const int tid = threadIdx.x;
    if (MODE == 0) {
        b4 = __ldcg((const float4*)&g_y[(kb + tid / 17) * RP + 4 * (tid % 17)]);
        if (tid < 16)
            be = __ldcg((const float4*)&g_y[(kb + 15) * RP + 4 * (tid + 1)]);
    } else {
        b4 = __ldcg((const float4*)&g_C[(tid >> 2) * 1536 + kb + 4 * (tid & 3)]);
        if (tid < 4)
            be = __ldcg((const float4*)&g_C[64 * 1536 + kb + 4 * tid]);
    }
}

template<int MODE>
__device__ __forceinline__ void b_store(float* Bs, float4 b4, float4 be) {
    const int tid = threadIdx.x;
    if (MODE == 0) {
        *(float4*)&Bs[(tid / 17) * 72 + 4 * (tid % 17)] = tf32r4(b4);
        if (tid < 16)
            *(float4*)&Bs[15 * 72 + 4 * (tid + 1)] = tf32r4(be);
    } else {
        int s = tid >> 2, cq = tid & 3;
        Bs[(4 * cq + 0) * 72 + s] = tf32r(b4.x);
        Bs[(4 * cq + 1) * 72 + s] = tf32r(b4.y);
        Bs[(4 * cq + 2) * 72 + s] = tf32r(b4.z);
        Bs[(4 * cq + 3) * 72 + s] = tf32r(b4.w);
        if (tid < 4) {
            Bs[(4 * tid + 0) * 72 + 64] = tf32r(be.x);
            Bs[(4 * tid + 1) * 72 + 64] = tf32r(be.y);
            Bs[(4 * tid + 2) * 72 + 64] = tf32r(be.z);
            Bs[(4 * tid + 3) * 72 + 64] = tf32r(be.w);
        }
        if (tid < 48) Bs[(tid / 3) * 72 + 65 + tid % 3] = 0.f;
    }
    if (tid < 16) *(float4*)&Bs[tid * 72 + 68] = make_float4(0.f, 0.f, 0.f, 0.f);
}

template<int NCH, int MODE>
__device__ __forceinline__ void gemm_item(float* sm, const float* __restrict__ A,
        int mbase, int kb0, float* __restrict__ outp) {
    const int tid = threadIdx.x, lane = tid & 31, w = tid >> 5;
    const int gid = lane >> 2, tig = lane & 3;
    float* Bb[2] = { sm, sm + 1152 };
    float* Tr = sm + 2304;   // [64][72]
    const int mfw = w & 3, kfw = w >> 2;
    const int kr = kfw * 8, mc = mfw * 16 + gid;

    float4 aR[2], b4[2], be[2];
    // prologue
    b_prefetch<MODE>(kb0, b4[0], be[0]);
    a_prefetch<MODE>(A, mbase, kb0, mc, kr, tig, aR[0]);
    if (NCH > 1) {
        b_prefetch<MODE>(kb0 + 16, b4[1], be[1]);
        a_prefetch<MODE>(A, mbase, kb0 + 16, mc, kr, tig, aR[1]);
    }
    __syncthreads();                    // guard smem vs previous item
    b_store<MODE>(Bb[0], b4[0], be[0]);
    __syncthreads();

    float d[9][4];
#pragma unroll
    for (int i = 0; i < 9; i++)
#pragma unroll
        for (int j = 0; j < 4; j++) d[i][j] = 0.f;

#pragma unroll
    for (int c = 0; c < NCH; c++) {
        const float* Bs = Bb[c & 1];
        uint32_t a0 = tf32u(aR[c & 1].x);
        uint32_t a1 = tf32u(aR[c & 1].y);
        uint32_t a2 = tf32u(aR[c & 1].z);
        uint32_t a3 = tf32u(aR[c & 1].w);
#pragma unroll
        for (int ns = 0; ns < 9; ns++) {
            uint32_t b0 = __float_as_uint(Bs[(kr + tig) * 72 + 8 * ns + gid]);
            uint32_t b1 = __float_as_uint(Bs[(kr + tig + 4) * 72 + 8 * ns + gid]);
            MMA_TF32(d[ns], a0, a1, a2, a3, b0, b1);
        }
        if (c + 2 < NCH)
            a_prefetch<MODE>(A, mbase, kb0 + (c + 2) * 16, mc, kr, tig, aR[c & 1]);
        if (c + 1 < NCH) {
            b_store<MODE>(Bb[(c + 1) & 1], b4[(c + 1) & 1], be[(c + 1) & 1]);
            if (c + 2 < NCH)
                b_prefetch<MODE>(kb0 + (c + 2) * 16, b4[c & 1], be[c & 1]);
            __syncthreads();
        }
    }
    // combine k-halves in Tr: kf=0 stores, kf=1 adds
    __syncthreads();
    if (kfw == 0) {
#pragma unroll
        for (int ns = 0; ns < 9; ns++) {
            int cc = 8 * ns + tig * 2;
            *(float2*)&Tr[(mfw * 16 + gid) * 72 + cc]     = make_float2(d[ns][0], d[ns][1]);
            *(float2*)&Tr[(mfw * 16 + gid + 8) * 72 + cc] = make_float2(d[ns][2], d[ns][3]);
        }
    }
    __syncthreads();
    if (kfw == 1) {
#pragma unroll
        for (int ns = 0; ns < 9; ns++) {
            int cc = 8 * ns + tig * 2;
            float2* p0 = (float2*)&Tr[(mfw * 16 + gid) * 72 + cc];
            float2 v0 = *p0; v0.x += d[ns][0]; v0.y += d[ns][1]; *p0 = v0;
            float2* p1 = (float2*)&Tr[(mfw * 16 + gid + 8) * 72 + cc];
            float2 v1 = *p1; v1.x += d[ns][2]; v1.y += d[ns][3]; *p1 = v1;
        }
    }
    __syncthreads();
    // vector copy out: 64 rows x 17 float4 (Tr stride 72 -> global 68)
    for (int i = tid; i < 1088; i += NT) {
        int r = i / 17, c4 = i % 17;
        *(float4*)&outp[(mbase + r) * RP + 4 * c4] = *(const float4*)&Tr[r * 72 + 4 * c4];
    }
}

// ------------------------- prep: g_y = emb*x (padded) ------------------------
__device__ void phase_prep(const float* __restrict__ inp, const float* __restrict__ emb) {
    for (int i = blockIdx.x * NT + threadIdx.x; i < HSP; i += NB * NT) {
        int h = i / RP, s = i - h * RP;
        float v = 0.f;
        if (s < 64)       v = emb[h * 65 + s] * __ldg(&inp[s]);
        else if (s == 64) v = emb[h * 65 + 64];
        g_y[i] = v;
    }
}

// ------------------------- kqv phase ----------------------------------------
template<int LAYER>
__device__ void phase_kqv(float* sm, const float* __restrict__ wK,
                          const float* __restrict__ wQ, const float* __restrict__ wV) {
    constexpr int nmats = (LAYER == 1) ? 9 : 3;
    constexpr int nkz   = (LAYER == 1) ? 4 : 8;
    constexpr int kspan = 512 / nkz;
    constexpr int per   = nmats * 8;
    constexpr int items = per * nkz;
    for (int it = blockIdx.x; it < items; it += NB) {
        int kz = it / per, rem = it - kz * per;
        int mat = rem >> 3, mtile = rem & 7;
        int type = (LAYER == 1) ? (mat % 3) : mat;
        int head = (LAYER == 1) ? (mat / 3) : 2;
        const float* A = ((type == 0) ? wK : (type == 1) ? wQ : wV) + head * 262144;
        gemm_item<kspan / 16, 0>(sm, A, mtile * 64, kz * kspan, &g_P[kz][mat][0]);
    }
}

// ------------ logits phase (h-chunk 64; folds kz partials at load) ----------
template<int LAYER>
__device__ void phase_logits(float* sm) {
    float* Ks = sm;            // [64][68]
    float* Qs = sm + 4352;
    float* Sm = sm + 8704;     // [65][68]
    const int tid = threadIdx.x, lane = tid & 31, w = tid >> 5;
    constexpr int slots = (LAYER == 1) ? 3 : 1;
    constexpr int nz    = (LAYER == 1) ? 4 : 8;
    constexpr int items = slots * 8;
    for (int it = blockIdx.x; it < items; it += NB) {
        int slot = it >> 3, hcc = it & 7, h0 = hcc * 64;
        int matK = (LAYER == 1) ? slot * 3 : 0;
        int matQ = matK + 1;
        __syncthreads();
        for (int i = tid; i < 1088; i += NT) {
            float4 k4 = __ldcg((const float4*)&g_P[0][matK][h0 * RP + 4 * i]);
            float4 q4 = __ldcg((const float4*)&g_P[0][matQ][h0 * RP + 4 * i]);
#pragma unroll
            for (int z = 1; z < nz; z++) {
                float4 u = __ldcg((const float4*)&g_P[z][matK][h0 * RP + 4 * i]);
                k4.x += u.x; k4.y += u.y; k4.z += u.z; k4.w += u.w;
                float4 v = __ldcg((const float4*)&g_P[z][matQ][h0 * RP + 4 * i]);
                q4.x += v.x; q4.y += v.y; q4.z += v.z; q4.w += v.w;
            }
            *(float4*)&Ks[4 * i] = k4;
            *(float4*)&Qs[4 * i] = q4;
        }
        if (tid < 65) { Sm[tid * RP + 65] = 0.f; Sm[tid * RP + 66] = 0.f; Sm[tid * RP + 67] = 0.f; }
        __syncthreads();
        ULL r0[4] = {0,0,0,0}, r1[4] = {0,0,0,0}, r2[4] = {0,0,0,0};
        float u0 = 0.f, u1 = 0.f, u2 = 0.f;
        for (int h = 0; h < 64; h++) {
            float k0 = Ks[h * RP + lane];
            float k1 = Ks[h * RP + 32 + lane];
            float k2 = Ks[h * RP + 64];
            ULL p0, p1, p2;
            PACK2(p0, k0); PACK2(p1, k1); PACK2(p2, k2);
            ulonglong2 qa = *(const ulonglong2*)(Qs + h * RP + 8 * w);
            ulonglong2 qb = *(const ulonglong2*)(Qs + h * RP + 8 * w + 4);
            FMA2(r0[0], p0, qa.x); FMA2(r0[1], p0, qa.y);
            FMA2(r0[2], p0, qb.x); FMA2(r0[3], p0, qb.y);
            FMA2(r1[0], p1, qa.x); FMA2(r1[1], p1, qa.y);
            FMA2(r1[2], p1, qb.x); FMA2(r1[3], p1, qb.y);
            FMA2(r2[0], p2, qa.x); FMA2(r2[1], p2, qa.y);
            FMA2(r2[2], p2, qb.x); FMA2(r2[3], p2, qb.y);
            if (w == 0) {
                float q64 = Qs[h * RP + 64];
                u0 = fmaf(k0, q64, u0); u1 = fmaf(k1, q64, u1); u2 = fmaf(k2, q64, u2);
            }
        }
        *(ulonglong2*)(Sm + lane * RP + 8 * w)     = make_ulonglong2(r0[0], r0[1]);
        *(ulonglong2*)(Sm + lane * RP + 8 * w + 4) = make_ulonglong2(r0[2], r0[3]);
        *(ulonglong2*)(Sm + (lane + 32) * RP + 8 * w)     = make_ulonglong2(r1[0], r1[1]);
        *(ulonglong2*)(Sm + (lane + 32) * RP + 8 * w + 4) = make_ulonglong2(r1[2], r1[3]);
        if (lane == 0) {
            *(ulonglong2*)(Sm + 64 * RP + 8 * w)     = make_ulonglong2(r2[0], r2[1]);
            *(ulonglong2*)(Sm + 64 * RP + 8 * w + 4) = make_ulonglong2(r2[2], r2[3]);
        }
        if (w == 0) {
            Sm[lane * RP + 64] = u0;
            Sm[(lane + 32) * RP + 64] = u1;
            if (lane == 0) Sm[64 * RP + 64] = u2;
        }
        __syncthreads();
        float* Lp = &g_Lp[hcc][slot][0];
        for (int i = tid; i < 1105; i += NT)
            *(float4*)&Lp[4 * i] = *(const float4*)&Sm[4 * i];
    }
}

// ---- att phase (softmax fused; folds hcc logits partials + kz V partials) --
template<int LAYER>
__device__ void phase_att(float* sm) {
    float* Ls = sm;            // [65][68]
    float* Vs = sm + 4420;     // [32][68]
    const int tid = threadIdx.x, lane = tid & 31, w = tid >> 5;
    constexpr int slots = (LAYER == 1) ? 3 : 1;
    constexpr int nz    = (LAYER == 1) ? 4 : 8;
    constexpr int items = slots * 16;
    for (int it = blockIdx.x; it < items; it += NB) {
        int slot = it >> 4, hc = it & 15, h0 = hc * 32;
        int matV = (LAYER == 1) ? slot * 3 + 2 : 2;
        int col0 = (LAYER == 1) ? slot * 512 : 1024;
        __syncthreads();
        for (int i = tid; i < 1105; i += NT) {
            float4 l4 = __ldcg((const float4*)&g_Lp[0][slot][0] + i);
#pragma unroll
            for (int c = 1; c < 8; c++) {
                float4 u = __ldcg((const float4*)&g_Lp[c][slot][0] + i);
                l4.x += u.x; l4.y += u.y; l4.z += u.z; l4.w += u.w;
            }
            ((float4*)Ls)[i] = l4;
        }
        for (int i = tid; i < 544; i += NT) {
            float4 v4 = __ldcg((const float4*)&g_P[0][matV][h0 * RP] + i);
#pragma unroll
            for (int z = 1; z < nz; z++) {
                float4 u = __ldcg((const float4*)&g_P[z][matV][h0 * RP] + i);
                v4.x += u.x; v4.y += u.y; v4.z += u.z; v4.w += u.w;
            }
            ((float4*)Vs)[i] = v4;
        }
        __syncthreads();
        if (tid < 32) { Vs[tid * RP + 65] = 0.f; Vs[tid * RP + 66] = 0.f; Vs[tid * RP + 67] = 0.f; }
        __syncthreads();
        for (int a = w; a < 65; a += 8) {
            float e0 = Ls[a * RP + lane];
            float e1 = Ls[a * RP + 32 + lane];
            float e2 = (lane == 0) ? Ls[a * RP + 64] : -3.0e38f;
            float mx = fmaxf(e0, fmaxf(e1, e2));
#pragma unroll
            for (int off = 16; off > 0; off >>= 1)
                mx = fmaxf(mx, __shfl_xor_sync(0xffffffffu, mx, off));
            float x0 = expf(e0 - mx);
            float x1 = expf(e1 - mx);
            float x2 = (lane == 0) ? expf(e2 - mx) : 0.f;
            float ssum = x0 + x1 + x2;
#pragma unroll
            for (int off = 16; off > 0; off >>= 1)
                ssum += __shfl_xor_sync(0xffffffffu, ssum, off);
            float inv = 1.0f / ssum;
            Ls[a * RP + lane] = x0 * inv;
            Ls[a * RP + 32 + lane] = x1 * inv;
            if (lane == 0) Ls[a * RP + 64] = x2 * inv;
        }
        __syncthreads();
        ULL acc[8] = {0,0,0,0,0,0,0,0};
        ULL acc64 = 0;
        const float* Vrow = Vs + lane * RP;
        for (int p = 0; p < 34; p++) {
            ULL vv = *(const ULL*)(Vrow + 2 * p);
#pragma unroll
            for (int j = 0; j < 8; j++) {
                ULL lp = *(const ULL*)(Ls + (8 * w + j) * RP + 2 * p);
                FMA2(acc[j], lp, vv);
            }
            if (w == 0) {
                ULL l64 = *(const ULL*)(Ls + 64 * RP + 2 * p);
                FMA2(acc64, l64, vv);
            }
        }
#pragma unroll
        for (int j = 0; j < 8; j++) {
            float lo, hi; UNPK2(lo, hi, acc[j]);
            g_C[(8 * w + j) * 1536 + col0 + h0 + lane] = lo + hi;
        }
        if (w == 0) {
            float lo, hi; UNPK2(lo, hi, acc64);
            g_C[64 * 1536 + col0 + h0 + lane] = lo + hi;
        }
    }
}

// ------------------------- linear phase -------------------------------------
__device__ void phase_linear(float* sm, const float* __restrict__ W) {
    for (int it = blockIdx.x; it < 192; it += NB) {
        int cc = it >> 3, mtile = it & 7;
        gemm_item<4, 1>(sm, W, mtile * 64, cc * 64, &g_lp[cc][0]);
    }
}

// ------------------------- reduce + relu -> g_y ------------------------------
__device__ void phase_rr() {
    for (int j = blockIdx.x * NT + threadIdx.x; j < HSP / 4; j += NB * NT) {
        float4 v = __ldcg((const float4*)&g_lp[0][4 * j]);
#pragma unroll
        for (int c = 1; c < 24; c++) {
            float4 u = __ldcg((const float4*)&g_lp[c][4 * j]);
            v.x += u.x; v.y += u.y; v.z += u.z; v.w += u.w;
        }
        v.x = fmaxf(v.x, 0.f); v.y = fmaxf(v.y, 0.f);
        v.z = fmaxf(v.z, 0.f); v.w = fmaxf(v.w, 0.f);
        *(float4*)&g_y[4 * j] = v;
    }
}

// ------------------------- final chain --------------------------------------
__device__ void phase_fc1(float* sm, const float* __restrict__ W3) {   // [1536][1024]
    float* Crs = sm;            // [192]
    float4* Rs4 = (float4*)(sm + 192);  // [256] float4
    const int tid = threadIdx.x;
    for (int it = blockIdx.x; it < 64; it += NB) {
        int jt = it & 7, cc = it >> 3;
        int c0 = cc * 192, j0 = jt * 128;
        __syncthreads();
        for (int i = tid; i < 192; i += NT)
            Crs[i] = __ldcg(&g_C[64 * 1536 + c0 + i]);
        __syncthreads();
        int j = j0 + 4 * (tid & 31);
        int cg = tid >> 5;
        float4 acc = make_float4(0.f, 0.f, 0.f, 0.f);
#pragma unroll 4
        for (int c = cg * 24; c < cg * 24 + 24; c++) {
            float cr = Crs[c];
            float4 w4 = *(const float4*)&W3[(c0 + c) * 1024 + j];
            acc.x = fmaf(cr, w4.x, acc.x); acc.y = fmaf(cr, w4.y, acc.y);
            acc.z = fmaf(cr, w4.z, acc.z); acc.w = fmaf(cr, w4.w, acc.w);
        }
        Rs4[tid] = acc;
        __syncthreads();
        if (tid < 32) {
            float4 s = Rs4[tid];
#pragma unroll
            for (int g = 1; g < 8; g++) {
                float4 u = Rs4[tid + 32 * g];
                s.x += u.x; s.y += u.y; s.z += u.z; s.w += u.w;
            }
            *(float4*)&g_zp[cc][j0 + 4 * tid] = s;
        }
    }
}

__device__ void phase_ft(float* sm, const float* __restrict__ W4) {   // [1024][512]
    float* zs = sm;
    float* Rs = sm + 1024;
    const int tid = threadIdx.x, lane = tid & 31, w = tid >> 5;
    for (int it = blockIdx.x; it < 4; it += NB) {
        int h0 = it * 128;
        __syncthreads();
        for (int i = tid; i < 1024; i += NT) {
            float v = 0.f;
#pragma unroll
            for (int c = 0; c < 8; c++) v += __ldcg(&g_zp[c][i]);
            zs[i] = fmaxf(v, 0.f);
        }
        __syncthreads();
        int hh = h0 + lane * 4;
        float4 a = make_float4(0.f, 0.f, 0.f, 0.f);
#pragma unroll 4
        for (int k = w * 128; k < w * 128 + 128; k++) {
            float zv = zs[k];
            float4 wr = *(const float4*)(&W4[k * 512 + hh]);
            a.x = fmaf(zv, wr.x, a.x); a.y = fmaf(zv, wr.y, a.y);
            a.z = fmaf(zv, wr.z, a.z); a.w = fmaf(zv, wr.w, a.w);
        }
        Rs[w * 128 + lane * 4 + 0] = a.x;
        Rs[w * 128 + lane * 4 + 1] = a.y;
        Rs[w * 128 + lane * 4 + 2] = a.z;
        Rs[w * 128 + lane * 4 + 3] = a.w;
        __syncthreads();
        if (tid < 128) {
            float s = 0.f;
#pragma unroll
            for (int ww = 0; ww < 8; ww++) s += Rs[ww * 128 + tid];
            g_t[h0 + tid] = tanhf(s);
        }
    }
}

__device__ void phase_fout(float* sm, const float* __restrict__ W5,
                           float* __restrict__ out) {   // [512][64]
    float* ts = sm;
    float* Rs = sm + 512;
    const int tid = threadIdx.x, lane = tid & 31, w = tid >> 5;
    for (int i = tid; i < 512; i += NT) ts[i] = __ldcg(&g_t[i]);
    __syncthreads();
    float acc0 = 0.f, acc1 = 0.f;
    for (int k = w * 64; k < w * 64 + 64; k++) {
        float tv = ts[k];
        acc0 = fmaf(tv, W5[k * 64 + lane], acc0);
        acc1 = fmaf(tv, W5[k * 64 + 32 + lane], acc1);
    }
    Rs[w * 64 + lane] = acc0;
    Rs[w * 64 + 32 + lane] = acc1;
    __syncthreads();
    if (tid < 64) {
        float s = 0.f;
#pragma unroll
        for (int ww = 0; ww < 8; ww++) s += Rs[ww * 64 + tid];
        out[tid] = s;
    }
}

// =============================================================================
__global__ __launch_bounds__(NT, 2)
void persist_kernel(const float* __restrict__ inp, const float* __restrict__ emb,
                    const float* __restrict__ wk, const float* __restrict__ wq,
                    const float* __restrict__ wv,
                    const float* __restrict__ l1, const float* __restrict__ l2,
                    const float* __restrict__ l3, const float* __restrict__ l4,
                    const float* __restrict__ l5, float* __restrict__ out) {
    __shared__ __align__(16) float sm[SMEM_F];
    const int HH = 512 * 512 * 3;

    pf_range(wk, 786432); pf_range(wk + 1310720, 262144); pf_range(wk + 2097152, 262144);
    pf_range(wq, 786432); pf_range(wq + 1310720, 262144); pf_range(wq + 2097152, 262144);
    pf_range(wv, 786432); pf_range(wv + 1310720, 262144); pf_range(wv + 2097152, 262144);
    pf_range(l1, 786432); pf_range(l2, 786432);
    pf_range(l3, 1572864); pf_range(l4, 524288); pf_range(l5, 32768);
    phase_prep(inp, emb);                            gbar(15);

    // ---- layer 1 ----
    phase_kqv<1>(sm, wk, wq, wv);                    gbar(0);
    phase_logits<1>(sm);                             gbar(1);
    phase_att<1>(sm);                                gbar(2);
    phase_linear(sm, l1);                            gbar(3);
    phase_rr();                                      gbar(4);
    // ---- layer 2 ----
    phase_kqv<2>(sm, wk + HH, wq + HH, wv + HH);     gbar(5);
    phase_logits<2>(sm);                             gbar(6);
    phase_att<2>(sm);                                gbar(7);
    phase_linear(sm, l2);                            gbar(8);
    phase_rr();                                      gbar(9);
    // ---- layer 3 ----
    phase_kqv<3>(sm, wk + 2 * HH, wq + 2 * HH, wv + 2 * HH);  gbar(10);
    phase_logits<3>(sm);                             gbar(11);
    phase_att<3>(sm);                                gbar(12);
    // ---- final chain ----
    phase_fc1(sm, l3);                               gbar(13);
    phase_ft(sm, l4);                                gbar(14);
    if (blockIdx.x == 0) phase_fout(sm, l5, out);
}

// ------------------------- launcher ----------------------------------------
extern "C" void kernel_launch(void* const* d_in, const int* in_sizes, int n_in,
                              void* d_out, int out_size) {
    const float *inp = 0, *emb = 0, *l3 = 0, *l4 = 0, *l5 = 0;
    const float *tri[3] = {0, 0, 0};  int ntri = 0;
    const float *pr[2]  = {0, 0};     int npr  = 0;
    for (int i = 0; i < n_in; i++) {
        const float* p = (const float*)d_in[i];
        switch (in_sizes[i]) {
            case 64:      inp = p; break;
            case 33280:   emb = p; break;
            case 2359296: if (ntri < 3) tri[ntri++] = p; break;
            case 786432:  if (npr  < 2) pr[npr++]   = p; break;
            case 1572864: l3 = p; break;
            case 524288:  l4 = p; break;
            case 32768:   l5 = p; break;
            default: break;
        }
    }
    const float *wq, *wk, *wv;
    if (n_in > 0 && in_sizes[0] == 33280) { wk = tri[0]; wq = tri[1]; wv = tri[2]; }
    else                                  { wq = tri[0]; wk = tri[1]; wv = tri[2]; }
    const float *l1 = pr[0], *l2 = pr[1];
    float* out = (float*)d_out;

    persist_kernel<<<NB, NT>>>(inp, emb, wk, wq, wv, l1, l2, l3, l4, l5, out);
}

// round 15
// speedup vs baseline: 1.0954x; 1.0954x over previous
#include <cuda_runtime.h>
#include <stdint.h>
#include <math.h>

#define NB   296
#define NT   256
#define RP   68                 // global padded row stride (17 float4)
#define HSP  (512*RP)
#define LSZ  (65*RP)
#define ULL  unsigned long long

// ------------------------- scratch (device globals) -------------------------
__device__ float g_y[HSP];             // current y [512][68] (pad cols always 0)
__device__ float g_P[8][9][HSP];       // kqv partials [kz][mat]
__device__ float g_Lp[8][3][LSZ];      // logits partials [hcc][slot]
__device__ float g_C[65*1536];         // concat buffer
__device__ float g_lp[24][HSP];        // linear partials [cc]
__device__ float g_zp[8][1024];
__device__ float g_t[512];
__device__ ULL   g_bar[24];

// ------------------------- helpers ------------------------------------------
#define FMA2(acc, a, b) asm("fma.rn.f32x2 %0, %1, %2, %0;" : "+l"(acc) : "l"(a), "l"(b))
#define PACK2(d, x)     asm("mov.b64 %0, {%1, %1};" : "=l"(d) : "f"(x))
#define UNPK2(lo, hi, v) asm("mov.b64 {%0, %1}, %2;" : "=f"(lo), "=f"(hi) : "l"(v))

#define MMA_TF32(d, a0, a1, a2, a3, b0, b1) \
    asm("mma.sync.aligned.m16n8k8.row.col.f32.tf32.tf32.f32 " \
        "{%0,%1,%2,%3}, {%4,%5,%6,%7}, {%8,%9}, {%0,%1,%2,%3};" \
        : "+f"(d[0]), "+f"(d[1]), "+f"(d[2]), "+f"(d[3]) \
        : "r"(a0), "r"(a1), "r"(a2), "r"(a3), "r"(b0), "r"(b1))

__device__ __forceinline__ float tf32r(float f) {
    uint32_t u;
    asm("cvt.rna.tf32.f32 %0, %1;" : "=r"(u) : "f"(f));
    return __uint_as_float(u);
}
__device__ __forceinline__ float4 tf32r4(float4 v) {
    return make_float4(tf32r(v.x), tf32r(v.y), tf32r(v.z), tf32r(v.w));
}

// release/acquire grid barrier (CG grid.sync pattern; bar.sync cumulativity)
__device__ __forceinline__ void gbar(int k) {
    __syncthreads();
    if (threadIdx.x == 0) {
        ULL* p = &g_bar[k];
        ULL old, cur;
        asm volatile("atom.release.gpu.add.u64 %0, [%1], 1;"
                     : "=l"(old) : "l"(p) : "memory");
        ULL target = old - (old % (ULL)NB) + (ULL)NB;
        do {
            asm volatile("ld.acquire.gpu.u64 %0, [%1];"
                         : "=l"(cur) : "l"(p) : "memory");
        } while (cur < target);
    }
    __syncthreads();
}

__device__ __forceinline__ void pf_range(const float* p, int nfloat) {
    int lines = nfloat >> 5;
    for (int i = blockIdx.x * NT + threadIdx.x; i < lines; i += NB * NT)
        asm volatile("prefetch.global.L2 [%0];" :: "l"(p + (i << 5)));
}

// shared pool (floats):
// GEMM: A0[1152] A1[1152] B0[1152] B1[1152] = 4608
// LOGITS Ks[4352] Qs[4352] Sm[4420] = 13124 ; ATT Ls[4420] Vs[2176] = 6596
#define SMEM_F 13124

// =============================================================================
// GEMM item via tf32 mma.sync m16n8k8, all-vector staged loads.
// Warp w owns (mf = w&3, ns-group = w>>2): full-K accumulation for its 4-5
// n-slices of 8 (group 0: ns 0-3, group 1: ns 4-8; col 64 in zero-padded
// slice 8). Results stored DIRECTLY to global (no Tr staging).
// MODE 0: A row-major W[m*512+k], B = g_y (padded). MODE 1: A k-major, B = g_C.
// =============================================================================
template<int MODE>
__device__ __forceinline__ void gemm_prefetch(const float* __restrict__ A,
        int mbase, int kb, float4& a4, float4& b4, float4& be) {
    const int tid = threadIdx.x;
    if (MODE == 0) {
        a4 = *(const float4*)&A[(mbase + (tid >> 2)) * 512 + kb + 4 * (tid & 3)];
        b4 = __ldcg((const float4*)&g_y[(kb + tid / 17) * RP + 4 * (tid % 17)]);
        if (tid < 16)
            be = __ldcg((const float4*)&g_y[(kb + 15) * RP + 4 * (tid + 1)]);
    } else {
        a4 = *(const float4*)&A[(kb + (tid >> 4)) * 512 + mbase + 4 * (tid & 15)];
        b4 = __ldcg((const float4*)&g_C[(tid >> 2) * 1536 + kb + 4 * (tid & 3)]);
        if (tid < 4)
            be = __ldcg((const float4*)&g_C[64 * 1536 + kb + 4 * tid]);
    }
}

template<int MODE>
__device__ __forceinline__ void gemm_store(float* At, float* Bs,
        float4 a4, float4 b4, float4 be) {
    const int tid = threadIdx.x;
    if (MODE == 0) {
        int m = tid >> 2, kq = tid & 3;
        At[(4 * kq + 0) * 72 + m] = tf32r(a4.x);
        At[(4 * kq + 1) * 72 + m] = tf32r(a4.y);
        At[(4 * kq + 2) * 72 + m] = tf32r(a4.z);
        At[(4 * kq + 3) * 72 + m] = tf32r(a4.w);
        *(float4*)&Bs[(tid / 17) * 72 + 4 * (tid % 17)] = tf32r4(b4);
        if (tid < 16)
            *(float4*)&Bs[15 * 72 + 4 * (tid + 1)] = tf32r4(be);
    } else {
        int k = tid >> 4, mq = tid & 15;
        *(float4*)&At[k * 72 + 4 * mq] = tf32r4(a4);
        int s = tid >> 2, cq = tid & 3;
        Bs[(4 * cq + 0) * 72 + s] = tf32r(b4.x);
        Bs[(4 * cq + 1) * 72 + s] = tf32r(b4.y);
        Bs[(4 * cq + 2) * 72 + s] = tf32r(b4.z);
        Bs[(4 * cq + 3) * 72 + s] = tf32r(b4.w);
        if (tid < 4) {
            Bs[(4 * tid + 0) * 72 + 64] = tf32r(be.x);
            Bs[(4 * tid + 1) * 72 + 64] = tf32r(be.y);
            Bs[(4 * tid + 2) * 72 + 64] = tf32r(be.z);
            Bs[(4 * tid + 3) * 72 + 64] = tf32r(be.w);
        }
        if (tid < 48) Bs[(tid / 3) * 72 + 65 + tid % 3] = 0.f;
    }
    // zero pad columns 68..71
    if (tid < 16) *(float4*)&Bs[tid * 72 + 68] = make_float4(0.f, 0.f, 0.f, 0.f);
}

template<int NCH, int MODE>
__device__ __forceinline__ void gemm_item(float* sm, const float* __restrict__ A,
        int mbase, int kb0, float* __restrict__ outp) {
    const int tid = threadIdx.x, lane = tid & 31, w = tid >> 5;
    const int gid = lane >> 2, tig = lane & 3;
    float* Ab0 = sm;          float* Ab1 = sm + 1152;
    float* Bb0 = sm + 2304;   float* Bb1 = sm + 3456;
    const int mfw = w & 3, ng = w >> 2;      // ns-group: 0 -> ns 0-3, 1 -> ns 4-8
    const int ns0 = ng ? 4 : 0;
    const int nsn = ng ? 5 : 4;
    const int mc = mfw * 16 + gid;

    float4 a4, b4, be;
    gemm_prefetch<MODE>(A, mbase, kb0, a4, b4, be);
    __syncthreads();                    // guard smem vs previous item
    gemm_store<MODE>(Ab0, Bb0, a4, b4, be);
    __syncthreads();

    float d[5][4];
#pragma unroll
    for (int i = 0; i < 5; i++)
#pragma unroll
        for (int j = 0; j < 4; j++) d[i][j] = 0.f;

#pragma unroll
    for (int c = 0; c < NCH; c++) {
        if (c + 1 < NCH)
            gemm_prefetch<MODE>(A, mbase, kb0 + (c + 1) * 16, a4, b4, be);
        const float* At = (c & 1) ? Ab1 : Ab0;
        const float* Bs = (c & 1) ? Bb1 : Bb0;
        // A fragments for BOTH k-halves
        uint32_t a00 = __float_as_uint(At[tig * 72 + mc]);
        uint32_t a01 = __float_as_uint(At[tig * 72 + mc + 8]);
        uint32_t a02 = __float_as_uint(At[(tig + 4) * 72 + mc]);
        uint32_t a03 = __float_as_uint(At[(tig + 4) * 72 + mc + 8]);
        uint32_t a10 = __float_as_uint(At[(8 + tig) * 72 + mc]);
        uint32_t a11 = __float_as_uint(At[(8 + tig) * 72 + mc + 8]);
        uint32_t a12 = __float_as_uint(At[(12 + tig) * 72 + mc]);
        uint32_t a13 = __float_as_uint(At[(12 + tig) * 72 + mc + 8]);
#pragma unroll
        for (int nsl = 0; nsl < 5; nsl++) {
            if (nsl < nsn) {
                int nc = 8 * (ns0 + nsl) + gid;
                uint32_t b00 = __float_as_uint(Bs[tig * 72 + nc]);
                uint32_t b01 = __float_as_uint(Bs[(tig + 4) * 72 + nc]);
                MMA_TF32(d[nsl], a00, a01, a02, a03, b00, b01);
                uint32_t b10 = __float_as_uint(Bs[(8 + tig) * 72 + nc]);
                uint32_t b11 = __float_as_uint(Bs[(12 + tig) * 72 + nc]);
                MMA_TF32(d[nsl], a10, a11, a12, a13, b10, b11);
            }
        }
        if (c + 1 < NCH) {
            gemm_store<MODE>((c & 1) ? Ab0 : Ab1, (c & 1) ? Bb0 : Bb1, a4, b4, be);
            __syncthreads();
        }
    }
    // direct global stores (full-K accumulators, no combining needed)
    const int r0 = mbase + mfw * 16 + gid;
#pragma unroll
    for (int nsl = 0; nsl < 5; nsl++) {
        int ns = ns0 + nsl;
        if (nsl < nsn && (ns < 8 || tig < 2)) {
            int cc = 8 * ns + tig * 2;
            *(float2*)&outp[r0 * RP + cc]       = make_float2(d[nsl][0], d[nsl][1]);
            *(float2*)&outp[(r0 + 8) * RP + cc] = make_float2(d[nsl][2], d[nsl][3]);
        }
    }
}

// ------------------------- prep: g_y = emb*x (padded) ------------------------
__device__ void phase_prep(const float* __restrict__ inp, const float* __restrict__ emb) {
    for (int i = blockIdx.x * NT + threadIdx.x; i < HSP; i += NB * NT) {
        int h = i / RP, s = i - h * RP;
        float v = 0.f;
        if (s < 64)       v = emb[h * 65 + s] * __ldg(&inp[s]);
        else if (s == 64) v = emb[h * 65 + 64];
        g_y[i] = v;
    }
}

// ------------------------- kqv phase ----------------------------------------
template<int LAYER>
__device__ void phase_kqv(float* sm, const float* __restrict__ wK,
                          const float* __restrict__ wQ, const float* __restrict__ wV) {
    constexpr int nmats = (LAYER == 1) ? 9 : 3;
    constexpr int nkz   = (LAYER == 1) ? 4 : 8;
    constexpr int kspan = 512 / nkz;
    constexpr int per   = nmats * 8;
    constexpr int items = per * nkz;
    for (int it = blockIdx.x; it < items; it += NB) {
        int kz = it / per, rem = it - kz * per;
        int mat = rem >> 3, mtile = rem & 7;
        int type = (LAYER == 1) ? (mat % 3) : mat;
        int head = (LAYER == 1) ? (mat / 3) : 2;
        const float* A = ((type == 0) ? wK : (type == 1) ? wQ : wV) + head * 262144;
        gemm_item<kspan / 16, 0>(sm, A, mtile * 64, kz * kspan, &g_P[kz][mat][0]);
    }
}

// ------------ logits phase (h-chunk 64; folds kz partials at load) ----------
template<int LAYER>
__device__ void phase_logits(float* sm) {
    float* Ks = sm;            // [64][68]
    float* Qs = sm + 4352;
    float* Sm = sm + 8704;     // [65][68]
    const int tid = threadIdx.x, lane = tid & 31, w = tid >> 5;
    constexpr int slots = (LAYER == 1) ? 3 : 1;
    constexpr int nz    = (LAYER == 1) ? 4 : 8;
    constexpr int items = slots * 8;
    for (int it = blockIdx.x; it < items; it += NB) {
        int slot = it >> 3, hcc = it & 7, h0 = hcc * 64;
        int matK = (LAYER == 1) ? slot * 3 : 0;
        int matQ = matK + 1;
        __syncthreads();
        for (int i = tid; i < 1088; i += NT) {
            float4 k4 = __ldcg((const float4*)&g_P[0][matK][h0 * RP + 4 * i]);
            float4 q4 = __ldcg((const float4*)&g_P[0][matQ][h0 * RP + 4 * i]);
#pragma unroll
            for (int z = 1; z < nz; z++) {
                float4 u = __ldcg((const float4*)&g_P[z][matK][h0 * RP + 4 * i]);
                k4.x += u.x; k4.y += u.y; k4.z += u.z; k4.w += u.w;
                float4 v = __ldcg((const float4*)&g_P[z][matQ][h0 * RP + 4 * i]);
                q4.x += v.x; q4.y += v.y; q4.z += v.z; q4.w += v.w;
            }
            *(float4*)&Ks[4 * i] = k4;
            *(float4*)&Qs[4 * i] = q4;
        }
        if (tid < 65) { Sm[tid * RP + 65] = 0.f; Sm[tid * RP + 66] = 0.f; Sm[tid * RP + 67] = 0.f; }
        __syncthreads();
        ULL r0[4] = {0,0,0,0}, r1[4] = {0,0,0,0}, r2[4] = {0,0,0,0};
        float u0 = 0.f, u1 = 0.f, u2 = 0.f;
        for (int h = 0; h < 64; h++) {
            float k0 = Ks[h * RP + lane];
            float k1 = Ks[h * RP + 32 + lane];
            float k2 = Ks[h * RP + 64];
            ULL p0, p1, p2;
            PACK2(p0, k0); PACK2(p1, k1); PACK2(p2, k2);
            ulonglong2 qa = *(const ulonglong2*)(Qs + h * RP + 8 * w);
            ulonglong2 qb = *(const ulonglong2*)(Qs + h * RP + 8 * w + 4);
            FMA2(r0[0], p0, qa.x); FMA2(r0[1], p0, qa.y);
            FMA2(r0[2], p0, qb.x); FMA2(r0[3], p0, qb.y);
            FMA2(r1[0], p1, qa.x); FMA2(r1[1], p1, qa.y);
            FMA2(r1[2], p1, qb.x); FMA2(r1[3], p1, qb.y);
            FMA2(r2[0], p2, qa.x); FMA2(r2[1], p2, qa.y);
            FMA2(r2[2], p2, qb.x); FMA2(r2[3], p2, qb.y);
            if (w == 0) {
                float q64 = Qs[h * RP + 64];
                u0 = fmaf(k0, q64, u0); u1 = fmaf(k1, q64, u1); u2 = fmaf(k2, q64, u2);
            }
        }
        *(ulonglong2*)(Sm + lane * RP + 8 * w)     = make_ulonglong2(r0[0], r0[1]);
        *(ulonglong2*)(Sm + lane * RP + 8 * w + 4) = make_ulonglong2(r0[2], r0[3]);
        *(ulonglong2*)(Sm + (lane + 32) * RP + 8 * w)     = make_ulonglong2(r1[0], r1[1]);
        *(ulonglong2*)(Sm + (lane + 32) * RP + 8 * w + 4) = make_ulonglong2(r1[2], r1[3]);
        if (lane == 0) {
            *(ulonglong2*)(Sm + 64 * RP + 8 * w)     = make_ulonglong2(r2[0], r2[1]);
            *(ulonglong2*)(Sm + 64 * RP + 8 * w + 4) = make_ulonglong2(r2[2], r2[3]);
        }
        if (w == 0) {
            Sm[lane * RP + 64] = u0;
            Sm[(lane + 32) * RP + 64] = u1;
            if (lane == 0) Sm[64 * RP + 64] = u2;
        }
        __syncthreads();
        float* Lp = &g_Lp[hcc][slot][0];
        for (int i = tid; i < 1105; i += NT)
            *(float4*)&Lp[4 * i] = *(const float4*)&Sm[4 * i];
    }
}

// ---- att phase (softmax fused; folds hcc logits partials + kz V partials) --
template<int LAYER>
__device__ void phase_att(float* sm) {
    float* Ls = sm;            // [65][68]
    float* Vs = sm + 4420;     // [32][68]
    const int tid = threadIdx.x, lane = tid & 31, w = tid >> 5;
    constexpr int slots = (LAYER == 1) ? 3 : 1;
    constexpr int nz    = (LAYER == 1) ? 4 : 8;
    constexpr int items = slots * 16;
    for (int it = blockIdx.x; it < items; it += NB) {
        int slot = it >> 4, hc = it & 15, h0 = hc * 32;
        int matV = (LAYER == 1) ? slot * 3 + 2 : 2;
        int col0 = (LAYER == 1) ? slot * 512 : 1024;
        __syncthreads();
        for (int i = tid; i < 1105; i += NT) {
            float4 l4 = __ldcg((const float4*)&g_Lp[0][slot][0] + i);
#pragma unroll
            for (int c = 1; c < 8; c++) {
                float4 u = __ldcg((const float4*)&g_Lp[c][slot][0] + i);
                l4.x += u.x; l4.y += u.y; l4.z += u.z; l4.w += u.w;
            }
            ((float4*)Ls)[i] = l4;
        }
        for (int i = tid; i < 544; i += NT) {
            float4 v4 = __ldcg((const float4*)&g_P[0][matV][h0 * RP] + i);
#pragma unroll
            for (int z = 1; z < nz; z++) {
                float4 u = __ldcg((const float4*)&g_P[z][matV][h0 * RP] + i);
                v4.x += u.x; v4.y += u.y; v4.z += u.z; v4.w += u.w;
            }
            ((float4*)Vs)[i] = v4;
        }
        __syncthreads();
        if (tid < 32) { Vs[tid * RP + 65] = 0.f; Vs[tid * RP + 66] = 0.f; Vs[tid * RP + 67] = 0.f; }
        __syncthreads();
        for (int a = w; a < 65; a += 8) {
            float e0 = Ls[a * RP + lane];
            float e1 = Ls[a * RP + 32 + lane];
            float e2 = (lane == 0) ? Ls[a * RP + 64] : -3.0e38f;
            float mx = fmaxf(e0, fmaxf(e1, e2));
#pragma unroll
            for (int off = 16; off > 0; off >>= 1)
                mx = fmaxf(mx, __shfl_xor_sync(0xffffffffu, mx, off));
            float x0 = expf(e0 - mx);
            float x1 = expf(e1 - mx);
            float x2 = (lane == 0) ? expf(e2 - mx) : 0.f;
            float ssum = x0 + x1 + x2;
#pragma unroll
            for (int off = 16; off > 0; off >>= 1)
                ssum += __shfl_xor_sync(0xffffffffu, ssum, off);
            float inv = 1.0f / ssum;
            Ls[a * RP + lane] = x0 * inv;
            Ls[a * RP + 32 + lane] = x1 * inv;
            if (lane == 0) Ls[a * RP + 64] = x2 * inv;
        }
        __syncthreads();
        ULL acc[8] = {0,0,0,0,0,0,0,0};
        ULL acc64 = 0;
        const float* Vrow = Vs + lane * RP;
        for (int p = 0; p < 34; p++) {
            ULL vv = *(const ULL*)(Vrow + 2 * p);
#pragma unroll
            for (int j = 0; j < 8; j++) {
                ULL lp = *(const ULL*)(Ls + (8 * w + j) * RP + 2 * p);
                FMA2(acc[j], lp, vv);
            }
            if (w == 0) {
                ULL l64 = *(const ULL*)(Ls + 64 * RP + 2 * p);
                FMA2(acc64, l64, vv);
            }
        }
#pragma unroll
        for (int j = 0; j < 8; j++) {
            float lo, hi; UNPK2(lo, hi, acc[j]);
            g_C[(8 * w + j) * 1536 + col0 + h0 + lane] = lo + hi;
        }
        if (w == 0) {
            float lo, hi; UNPK2(lo, hi, acc64);
            g_C[64 * 1536 + col0 + h0 + lane] = lo + hi;
        }
    }
}

// ------------------------- linear phase -------------------------------------
__device__ void phase_linear(float* sm, const float* __restrict__ W) {
    for (int it = blockIdx.x; it < 192; it += NB) {
        int cc = it >> 3, mtile = it & 7;
        gemm_item<4, 1>(sm, W, mtile * 64, cc * 64, &g_lp[cc][0]);
    }
}

// ------------------------- reduce + relu -> g_y ------------------------------
__device__ void phase_rr() {
    for (int j = blockIdx.x * NT + threadIdx.x; j < HSP / 4; j += NB * NT) {
        float4 v = __ldcg((const float4*)&g_lp[0][4 * j]);
#pragma unroll
        for (int c = 1; c < 24; c++) {
            float4 u = __ldcg((const float4*)&g_lp[c][4 * j]);
            v.x += u.x; v.y += u.y; v.z += u.z; v.w += u.w;
        }
        v.x = fmaxf(v.x, 0.f); v.y = fmaxf(v.y, 0.f);
        v.z = fmaxf(v.z, 0.f); v.w = fmaxf(v.w, 0.f);
        *(float4*)&g_y[4 * j] = v;
    }
}

// ------------------------- final chain --------------------------------------
__device__ void phase_fc1(float* sm, const float* __restrict__ W3) {   // [1536][1024]
    float* Crs = sm;            // [192]
    float4* Rs4 = (float4*)(sm + 192);  // [256] float4
    const int tid = threadIdx.x;
    for (int it = blockIdx.x; it < 64; it += NB) {
        int jt = it & 7, cc = it >> 3;
        int c0 = cc * 192, j0 = jt * 128;
        __syncthreads();
        for (int i = tid; i < 192; i += NT)
            Crs[i] = __ldcg(&g_C[64 * 1536 + c0 + i]);
        __syncthreads();
        int j = j0 + 4 * (tid & 31);
        int cg = tid >> 5;
        float4 acc = make_float4(0.f, 0.f, 0.f, 0.f);
#pragma unroll 4
        for (int c = cg * 24; c < cg * 24 + 24; c++) {
            float cr = Crs[c];
            float4 w4 = *(const float4*)&W3[(c0 + c) * 1024 + j];
            acc.x = fmaf(cr, w4.x, acc.x); acc.y = fmaf(cr, w4.y, acc.y);
            acc.z = fmaf(cr, w4.z, acc.z); acc.w = fmaf(cr, w4.w, acc.w);
        }
        Rs4[tid] = acc;
        __syncthreads();
        if (tid < 32) {
            float4 s = Rs4[tid];
#pragma unroll
            for (int g = 1; g < 8; g++) {
                float4 u = Rs4[tid + 32 * g];
                s.x += u.x; s.y += u.y; s.z += u.z; s.w += u.w;
            }
            *(float4*)&g_zp[cc][j0 + 4 * tid] = s;
        }
    }
}

__device__ void phase_ft(float* sm, const float* __restrict__ W4) {   // [1024][512]
    float* zs = sm;
    float* Rs = sm + 1024;
    const int tid = threadIdx.x, lane = tid & 31, w = tid >> 5;
    for (int it = blockIdx.x; it < 4; it += NB) {
        int h0 = it * 128;
        __syncthreads();
        for (int i = tid; i < 1024; i += NT) {
            float v = 0.f;
#pragma unroll
            for (int c = 0; c < 8; c++) v += __ldcg(&g_zp[c][i]);
            zs[i] = fmaxf(v, 0.f);
        }
        __syncthreads();
        int hh = h0 + lane * 4;
        float4 a = make_float4(0.f, 0.f, 0.f, 0.f);
#pragma unroll 4
        for (int k = w * 128; k < w * 128 + 128; k++) {
            float zv = zs[k];
            float4 wr = *(const float4*)(&W4[k * 512 + hh]);
            a.x = fmaf(zv, wr.x, a.x); a.y = fmaf(zv, wr.y, a.y);
            a.z = fmaf(zv, wr.z, a.z); a.w = fmaf(zv, wr.w, a.w);
        }
        Rs[w * 128 + lane * 4 + 0] = a.x;
        Rs[w * 128 + lane * 4 + 1] = a.y;
        Rs[w * 128 + lane * 4 + 2] = a.z;
        Rs[w * 128 + lane * 4 + 3] = a.w;
        __syncthreads();
        if (tid < 128) {
            float s = 0.f;
#pragma unroll
            for (int ww = 0; ww < 8; ww++) s += Rs[ww * 128 + tid];
            g_t[h0 + tid] = tanhf(s);
        }
    }
}

__device__ void phase_fout(float* sm, const float* __restrict__ W5,
                           float* __restrict__ out) {   // [512][64]
    float* ts = sm;
    float* Rs = sm + 512;
    const int tid = threadIdx.x, lane = tid & 31, w = tid >> 5;
    for (int i = tid; i < 512; i += NT) ts[i] = __ldcg(&g_t[i]);
    __syncthreads();
    float acc0 = 0.f, acc1 = 0.f;
    for (int k = w * 64; k < w * 64 + 64; k++) {
        float tv = ts[k];
        acc0 = fmaf(tv, W5[k * 64 + lane], acc0);
        acc1 = fmaf(tv, W5[k * 64 + 32 + lane], acc1);
    }
    Rs[w * 64 + lane] = acc0;
    Rs[w * 64 + 32 + lane] = acc1;
    __syncthreads();
    if (tid < 64) {
        float s = 0.f;
#pragma unroll
        for (int ww = 0; ww < 8; ww++) s += Rs[ww * 64 + tid];
        out[tid] = s;
    }
}

// =============================================================================
__global__ __launch_bounds__(NT, 2)
void persist_kernel(const float* __restrict__ inp, const float* __restrict__ emb,
                    const float* __restrict__ wk, const float* __restrict__ wq,
                    const float* __restrict__ wv,
                    const float* __restrict__ l1, const float* __restrict__ l2,
                    const float* __restrict__ l3, const float* __restrict__ l4,
                    const float* __restrict__ l5, float* __restrict__ out) {
    __shared__ __align__(16) float sm[SMEM_F];
    const int HH = 512 * 512 * 3;

    pf_range(wk, 786432); pf_range(wk + 1310720, 262144); pf_range(wk + 2097152, 262144);
    pf_range(wq, 786432); pf_range(wq + 1310720, 262144); pf_range(wq + 2097152, 262144);
    pf_range(wv, 786432); pf_range(wv + 1310720, 262144); pf_range(wv + 2097152, 262144);
    pf_range(l1, 786432); pf_range(l2, 786432);
    pf_range(l3, 1572864); pf_range(l4, 524288); pf_range(l5, 32768);
    phase_prep(inp, emb);                            gbar(15);

    // ---- layer 1 ----
    phase_kqv<1>(sm, wk, wq, wv);                    gbar(0);
    phase_logits<1>(sm);                             gbar(1);
    phase_att<1>(sm);                                gbar(2);
    phase_linear(sm, l1);                            gbar(3);
    phase_rr();                                      gbar(4);
    // ---- layer 2 ----
    phase_kqv<2>(sm, wk + HH, wq + HH, wv + HH);     gbar(5);
    phase_logits<2>(sm);                             gbar(6);
    phase_att<2>(sm);                                gbar(7);
    phase_linear(sm, l2);                            gbar(8);
    phase_rr();                                      gbar(9);
    // ---- layer 3 ----
    phase_kqv<3>(sm, wk + 2 * HH, wq + 2 * HH, wv + 2 * HH);  gbar(10);
    phase_logits<3>(sm);                             gbar(11);
    phase_att<3>(sm);                                gbar(12);
    // ---- final chain ----
    phase_fc1(sm, l3);                               gbar(13);
    phase_ft(sm, l4);                                gbar(14);
    if (blockIdx.x == 0) phase_fout(sm, l5, out);
}

// ------------------------- launcher ----------------------------------------
extern "C" void kernel_launch(void* const* d_in, const int* in_sizes, int n_in,
                              void* d_out, int out_size) {
    const float *inp = 0, *emb = 0, *l3 = 0, *l4 = 0, *l5 = 0;
    const float *tri[3] = {0, 0, 0};  int ntri = 0;
    const float *pr[2]  = {0, 0};     int npr  = 0;
    for (int i = 0; i < n_in; i++) {
        const float* p = (const float*)d_in[i];
        switch (in_sizes[i]) {
            case 64:      inp = p; break;
            case 33280:   emb = p; break;
            case 2359296: if (ntri < 3) tri[ntri++] = p; break;
            case 786432:  if (npr  < 2) pr[npr++]   = p; break;
            case 1572864: l3 = p; break;
            case 524288:  l4 = p; break;
            case 32768:   l5 = p; break;
            default: break;
        }
    }
    const float *wq, *wk, *wv;
    if (n_in > 0 && in_sizes[0] == 33280) { wk = tri[0]; wq = tri[1]; wv = tri[2]; }
    else                                  { wq = tri[0]; wk = tri[1]; wv = tri[2]; }
    const float *l1 = pr[0], *l2 = pr[1];
    float* out = (float*)d_out;

    persist_kernel<<<NB, NT>>>(inp, emb, wk, wq, wv, l1, l2, l3, l4, l5, out);
}